// round 14
// baseline (speedup 1.0000x reference)
#include <cuda_runtime.h>
#include <cuda_bf16.h>
#include <cstdint>
#include <cstddef>

#define N_QTOK 4096      // 128 query batches * 32 tokens
#define N_DTOK 16384     // 128 doc batches * 128 tokens
#define N_TOK  20480
#define DIM    128
#define HID    256
#define N_ETILE 320      // 20480 / 64 rows per embed tile

// bf16 normalized embeddings: rows 0..4095 = query tokens, 4096..20479 = doc
__device__ __align__(16) __nv_bfloat16 g_emb[(size_t)N_TOK * DIM];
__device__ unsigned g_ctr;   // embed steal counter; reset by sim_kernel

// ---------------------------------------------------------------------------
// PTX helpers (base sm_103 only — tcgen05 needs compute_103a virtual arch,
// which the harness does not use)
// ---------------------------------------------------------------------------
__device__ __forceinline__ void ldsm4(uint32_t& r0, uint32_t& r1,
                                      uint32_t& r2, uint32_t& r3, unsigned addr) {
    asm volatile("ldmatrix.sync.aligned.m8n8.x4.shared.b16 {%0,%1,%2,%3}, [%4];\n"
                 : "=r"(r0), "=r"(r1), "=r"(r2), "=r"(r3) : "r"(addr));
}
__device__ __forceinline__ void ldsm4t(uint32_t& r0, uint32_t& r1,
                                       uint32_t& r2, uint32_t& r3, unsigned addr) {
    asm volatile("ldmatrix.sync.aligned.m8n8.x4.trans.shared.b16 {%0,%1,%2,%3}, [%4];\n"
                 : "=r"(r0), "=r"(r1), "=r"(r2), "=r"(r3) : "r"(addr));
}
__device__ __forceinline__ void mma16816(float* c, const uint32_t* a,
                                         uint32_t b0, uint32_t b1) {
    asm volatile(
        "mma.sync.aligned.m16n8k16.row.col.f32.bf16.bf16.f32 "
        "{%0,%1,%2,%3}, {%4,%5,%6,%7}, {%8,%9}, {%0,%1,%2,%3};\n"
        : "+f"(c[0]), "+f"(c[1]), "+f"(c[2]), "+f"(c[3])
        : "r"(a[0]), "r"(a[1]), "r"(a[2]), "r"(a[3]), "r"(b0), "r"(b1));
}
__device__ __forceinline__ void cp_async16(unsigned saddr, const void* g) {
    asm volatile("cp.async.cg.shared.global [%0], [%1], 16;\n"
                 :: "r"(saddr), "l"(g) : "memory");
}
__device__ __forceinline__ void cp_commit() {
    asm volatile("cp.async.commit_group;\n" ::: "memory");
}
template <int N> __device__ __forceinline__ void cp_wait() {
    asm volatile("cp.async.wait_group %0;\n" :: "n"(N) : "memory");
}
__device__ __forceinline__ uint32_t smem_u32(const void* p) {
    uint32_t a;
    asm("{ .reg .u64 t; cvta.to.shared.u64 t, %1; cvt.u32.u64 %0, t; }"
        : "=r"(a) : "l"(p));
    return a;
}
__device__ __forceinline__ void cvt_hilo4(const float4& v,
                                          __nv_bfloat16* h, __nv_bfloat16* l) {
    float vv[4] = { v.x, v.y, v.z, v.w };
#pragma unroll
    for (int e = 0; e < 4; e++) {
        h[e] = __float2bfloat16(vv[e]);
        l[e] = __float2bfloat16(vv[e] - __bfloat162float(h[e]));
    }
}

// ---------------------------------------------------------------------------
// Kernel 1: projection + bias + L2 normalize (hi/lo bf16 split ~ fp32).
// REVERTED to R12's proven best: 320 tiles of 64 rows, grid 2*SMs, occ 2,
// warps 2(M) x 4(N), kc-pipelined (fp32 prefetch in regs during mma).
// ---------------------------------------------------------------------------
#define AK 72       // A smem k-stride (144B pitch, conflict-free)
#define WP 136      // W smem n-stride (272B pitch, conflict-free)
#define WB_ELEM (64 * WP)
#define AB_ELEM (64 * AK)
#define BUF_ELEM (2 * WB_ELEM + 2 * AB_ELEM)

__global__ __launch_bounds__(256, 2) void embed_kernel(
    const float* __restrict__ qh, const float* __restrict__ dh,
    const float* __restrict__ W, const float* __restrict__ bias)
{
    extern __shared__ char esm[];
    __nv_bfloat16* sb16 = (__nv_bfloat16*)esm;   // [2][BUF_ELEM]
    float* ssp = (float*)(esm + 2 * BUF_ELEM * 2);        // [64][4]
    unsigned* s_t = (unsigned*)(ssp + 64 * 4);

    const int tid  = threadIdx.x;
    const int lane = tid & 31, warp = tid >> 5;
    const int wm = warp >> 2, wn = warp & 3;

    unsigned uWhi[2], uWlo[2], uAhi[2], uAlo[2];
#pragma unroll
    for (int b = 0; b < 2; b++) {
        unsigned base = smem_u32(sb16 + (size_t)b * BUF_ELEM);
        uWhi[b] = base;
        uWlo[b] = base + WB_ELEM * 2;
        uAhi[b] = base + 2 * WB_ELEM * 2;
        uAlo[b] = base + (2 * WB_ELEM + AB_ELEM) * 2;
    }

    unsigned aoff[2];
#pragma unroll
    for (int mt = 0; mt < 2; mt++)
        aoff[mt] = (unsigned)((wm * 32 + mt * 16 + (lane & 15)) * AK
                              + (lane >> 4) * 8) * 2;
    const int bk = (lane & 7) + ((lane >> 3) & 1) * 8;
    const unsigned bnb = (unsigned)(wn * 32 + (lane >> 4) * 8) * 2;
    const int cbase = (lane & 3) * 2;

    for (;;) {
        __syncthreads();
        if (tid == 0) *s_t = atomicAdd(&g_ctr, 1u);
        __syncthreads();
        const unsigned t = *s_t;
        if (t >= N_ETILE) break;

        const int row0 = (int)t * 64;
        const float* src = (row0 < N_QTOK)
            ? (qh + (size_t)row0 * HID)
            : (dh + (size_t)(row0 - N_QTOK) * HID);

        {
#pragma unroll
            for (int j = 0; j < 8; j++) {
                int f = tid + j * 256, r = f >> 5, c4 = f & 31;
                float4 v = *(const float4*)(W + (size_t)r * DIM + c4 * 4);
                __nv_bfloat16 h[4], l[4];
                cvt_hilo4(v, h, l);
                unsigned off = (unsigned)(r * WP + c4 * 4) * 2;
                *(uint2*)(esm + uWhi[0] - smem_u32(esm) + off) = *(uint2*)h;
                *(uint2*)(esm + uWlo[0] - smem_u32(esm) + off) = *(uint2*)l;
            }
#pragma unroll
            for (int j = 0; j < 4; j++) {
                int f = tid + j * 256, r = f >> 4, cv = f & 15;
                float4 v = *(const float4*)(src + (size_t)r * HID + cv * 4);
                __nv_bfloat16 h[4], l[4];
                cvt_hilo4(v, h, l);
                unsigned off = (unsigned)(r * AK + cv * 4) * 2;
                *(uint2*)(esm + uAhi[0] - smem_u32(esm) + off) = *(uint2*)h;
                *(uint2*)(esm + uAlo[0] - smem_u32(esm) + off) = *(uint2*)l;
            }
        }
        __syncthreads();

        float acc[2][4][4];
#pragma unroll
        for (int mt = 0; mt < 2; mt++)
#pragma unroll
            for (int nt = 0; nt < 4; nt++)
#pragma unroll
                for (int r = 0; r < 4; r++) acc[mt][nt][r] = 0.f;

#pragma unroll
        for (int kc = 0; kc < 4; kc++) {
            const int cb = kc & 1, nb = cb ^ 1;

            float4 wreg[8], areg[4];
            if (kc < 3) {
                const int k0n = (kc + 1) * 64;
#pragma unroll
                for (int j = 0; j < 8; j++) {
                    int f = tid + j * 256, r = f >> 5, c4 = f & 31;
                    wreg[j] = *(const float4*)(W + (size_t)(k0n + r) * DIM + c4 * 4);
                }
#pragma unroll
                for (int j = 0; j < 4; j++) {
                    int f = tid + j * 256, r = f >> 4, cv = f & 15;
                    areg[j] = *(const float4*)(src + (size_t)r * HID + k0n + cv * 4);
                }
            }

#pragma unroll
            for (int ks = 0; ks < 4; ks++) {
                uint32_t ah0[4], ah1[4], al0[4], al1[4];
                ldsm4(ah0[0], ah0[1], ah0[2], ah0[3], uAhi[cb] + aoff[0] + ks * 32);
                ldsm4(ah1[0], ah1[1], ah1[2], ah1[3], uAhi[cb] + aoff[1] + ks * 32);
                ldsm4(al0[0], al0[1], al0[2], al0[3], uAlo[cb] + aoff[0] + ks * 32);
                ldsm4(al1[0], al1[1], al1[2], al1[3], uAlo[cb] + aoff[1] + ks * 32);
                const unsigned be = (unsigned)((ks * 16 + bk) * WP) * 2 + bnb;
                uint32_t bh0[4], bh1[4], bl0[4], bl1[4];
                ldsm4t(bh0[0], bh0[1], bh0[2], bh0[3], uWhi[cb] + be);
                ldsm4t(bh1[0], bh1[1], bh1[2], bh1[3], uWhi[cb] + be + 32);
                ldsm4t(bl0[0], bl0[1], bl0[2], bl0[3], uWlo[cb] + be);
                ldsm4t(bl1[0], bl1[1], bl1[2], bl1[3], uWlo[cb] + be + 32);

                mma16816(acc[0][0], ah0, bh0[0], bh0[1]);
                mma16816(acc[0][0], ah0, bl0[0], bl0[1]);
                mma16816(acc[0][0], al0, bh0[0], bh0[1]);
                mma16816(acc[0][1], ah0, bh0[2], bh0[3]);
                mma16816(acc[0][1], ah0, bl0[2], bl0[3]);
                mma16816(acc[0][1], al0, bh0[2], bh0[3]);
                mma16816(acc[0][2], ah0, bh1[0], bh1[1]);
                mma16816(acc[0][2], ah0, bl1[0], bl1[1]);
                mma16816(acc[0][2], al0, bh1[0], bh1[1]);
                mma16816(acc[0][3], ah0, bh1[2], bh1[3]);
                mma16816(acc[0][3], ah0, bl1[2], bl1[3]);
                mma16816(acc[0][3], al0, bh1[2], bh1[3]);

                mma16816(acc[1][0], ah1, bh0[0], bh0[1]);
                mma16816(acc[1][0], ah1, bl0[0], bl0[1]);
                mma16816(acc[1][0], al1, bh0[0], bh0[1]);
                mma16816(acc[1][1], ah1, bh0[2], bh0[3]);
                mma16816(acc[1][1], ah1, bl0[2], bl0[3]);
                mma16816(acc[1][1], al1, bh0[2], bh0[3]);
                mma16816(acc[1][2], ah1, bh1[0], bh1[1]);
                mma16816(acc[1][2], ah1, bl1[0], bl1[1]);
                mma16816(acc[1][2], al1, bh1[0], bh1[1]);
                mma16816(acc[1][3], ah1, bh1[2], bh1[3]);
                mma16816(acc[1][3], ah1, bl1[2], bl1[3]);
                mma16816(acc[1][3], al1, bh1[2], bh1[3]);
            }

            if (kc < 3) {
#pragma unroll
                for (int j = 0; j < 8; j++) {
                    int f = tid + j * 256, r = f >> 5, c4 = f & 31;
                    __nv_bfloat16 h[4], l[4];
                    cvt_hilo4(wreg[j], h, l);
                    unsigned off = (unsigned)(r * WP + c4 * 4) * 2;
                    asm volatile("st.shared.v2.b32 [%0], {%1, %2};\n" ::
                        "r"(uWhi[nb] + off),
                        "r"(*(uint32_t*)&h[0]), "r"(*(uint32_t*)&h[2]));
                    asm volatile("st.shared.v2.b32 [%0], {%1, %2};\n" ::
                        "r"(uWlo[nb] + off),
                        "r"(*(uint32_t*)&l[0]), "r"(*(uint32_t*)&l[2]));
                }
#pragma unroll
                for (int j = 0; j < 4; j++) {
                    int f = tid + j * 256, r = f >> 4, cv = f & 15;
                    __nv_bfloat16 h[4], l[4];
                    cvt_hilo4(areg[j], h, l);
                    unsigned off = (unsigned)(r * AK + cv * 4) * 2;
                    asm volatile("st.shared.v2.b32 [%0], {%1, %2};\n" ::
                        "r"(uAhi[nb] + off),
                        "r"(*(uint32_t*)&h[0]), "r"(*(uint32_t*)&h[2]));
                    asm volatile("st.shared.v2.b32 [%0], {%1, %2};\n" ::
                        "r"(uAlo[nb] + off),
                        "r"(*(uint32_t*)&l[0]), "r"(*(uint32_t*)&l[2]));
                }
            }
            __syncthreads();
        }

#pragma unroll
        for (int mt = 0; mt < 2; mt++) {
            float s0 = 0.f, s1 = 0.f;
#pragma unroll
            for (int nt = 0; nt < 4; nt++) {
                float2 bv = *(const float2*)(bias + wn * 32 + nt * 8 + cbase);
                acc[mt][nt][0] += bv.x; acc[mt][nt][1] += bv.y;
                acc[mt][nt][2] += bv.x; acc[mt][nt][3] += bv.y;
                s0 += acc[mt][nt][0] * acc[mt][nt][0]
                    + acc[mt][nt][1] * acc[mt][nt][1];
                s1 += acc[mt][nt][2] * acc[mt][nt][2]
                    + acc[mt][nt][3] * acc[mt][nt][3];
            }
            s0 += __shfl_xor_sync(0xffffffffu, s0, 1);
            s0 += __shfl_xor_sync(0xffffffffu, s0, 2);
            s1 += __shfl_xor_sync(0xffffffffu, s1, 1);
            s1 += __shfl_xor_sync(0xffffffffu, s1, 2);
            if ((lane & 3) == 0) {
                ssp[(wm * 32 + mt * 16 + (lane >> 2)) * 4 + wn] = s0;
                ssp[(wm * 32 + mt * 16 + 8 + (lane >> 2)) * 4 + wn] = s1;
            }
        }
        __syncthreads();
#pragma unroll
        for (int mt = 0; mt < 2; mt++) {
            const int r0 = wm * 32 + mt * 16 + (lane >> 2);
            const int r1 = r0 + 8;
            float ss0 = ssp[r0 * 4] + ssp[r0 * 4 + 1]
                      + ssp[r0 * 4 + 2] + ssp[r0 * 4 + 3];
            float ss1 = ssp[r1 * 4] + ssp[r1 * 4 + 1]
                      + ssp[r1 * 4 + 2] + ssp[r1 * 4 + 3];
            float inv0 = 1.f / fmaxf(sqrtf(ss0), 1e-12f);
            float inv1 = 1.f / fmaxf(sqrtf(ss1), 1e-12f);
#pragma unroll
            for (int nt = 0; nt < 4; nt++) {
                __nv_bfloat162 vA, vB;
                vA.x = __float2bfloat16(acc[mt][nt][0] * inv0);
                vA.y = __float2bfloat16(acc[mt][nt][1] * inv0);
                vB.x = __float2bfloat16(acc[mt][nt][2] * inv1);
                vB.y = __float2bfloat16(acc[mt][nt][3] * inv1);
                *(__nv_bfloat162*)(g_emb + (size_t)(row0 + r0) * DIM
                                   + wn * 32 + nt * 8 + cbase) = vA;
                *(__nv_bfloat162*)(g_emb + (size_t)(row0 + r1) * DIM
                                   + wn * 32 + nt * 8 + cbase) = vB;
            }
        }
    }
}

// ---------------------------------------------------------------------------
// Kernel 2: PERSISTENT fused similarity GEMM + max_t + sum_s — OCC 3.
// smem = Q (resident) + ONE doc buffer + red = 71.7KB -> 3 CTAs/SM.
// Mainloop: two N=64 passes per tile (acc 32 regs; ~70 live regs, fits the
// occ-3 cap). Doc tile for j+1 prefetched right after S2 of tile j (reads
// done); cp_wait<0> + S1 at iteration top. Inter-CTA overlap hides the load.
// ---------------------------------------------------------------------------
#define DSTR 136

__global__ __launch_bounds__(256, 3) void sim_kernel(float* __restrict__ out)
{
    extern __shared__ char smem[];
    __nv_bfloat16* sQ = (__nv_bfloat16*)smem;              // 128 x 136
    __nv_bfloat16* sD = sQ + 128 * DSTR;                   // 128 x 136 (single)
    float* red = (float*)(sD + 128 * DSTR);                // [2][8 warps][32]

    const int tid  = threadIdx.x;
    const int lane = tid & 31, warp = tid >> 5;
    const int wm = warp >> 1, wn = warp & 1;
    const unsigned G = gridDim.x, c = blockIdx.x;
    unsigned s = (4096u * c) / G;
    const unsigned e = (4096u * (c + 1)) / G;

    if (c == 0 && tid == 0) g_ctr = 0u;   // reset embed steal counter

    const unsigned uQ = smem_u32(sQ);
    const unsigned uD = smem_u32(sD);

    unsigned aoff[2];
#pragma unroll
    for (int mt = 0; mt < 2; mt++) {
        int row = wm * 32 + mt * 16 + (lane & 15);
        int col = (lane >> 4) * 8;
        aoff[mt] = uQ + (unsigned)(row * DSTR + col) * 2;
    }
    // b offsets: half h (64 cols) x group g (16 doc tokens in warp's 32)
    unsigned boff[2][2];
#pragma unroll
    for (int h = 0; h < 2; h++)
#pragma unroll
        for (int g = 0; g < 2; g++) {
            int row = h * 64 + wn * 32 + g * 16 + (lane & 7) + (lane >> 4) * 8;
            int col = ((lane >> 3) & 1) * 8;
            boff[h][g] = uD + (unsigned)(row * DSTR + col) * 2;
        }

    while (s < e) {
        const unsigned qg = s >> 7;
        const unsigned seg_e = min(e, (qg + 1) << 7);
        const int n = (int)(seg_e - s);
        const unsigned qb0 = qg * 4;
        const unsigned db_base = s & 127;

        {   // prefetch doc tile 0 (buffer dead: prior segment's last barrier)
            const __nv_bfloat16* dsrc =
                g_emb + (size_t)(N_QTOK + db_base * 128) * DIM;
#pragma unroll
            for (int j = 0; j < 8; j++) {
                int f = tid + j * 256, r = f >> 4, c8 = f & 15;
                cp_async16(uD + (unsigned)(r * DSTR + c8 * 8) * 2,
                           dsrc + (size_t)r * DIM + c8 * 8);
            }
            cp_commit();
        }
        {   // load Q tile for this segment (visible after j=0's S1)
            const __nv_bfloat16* qsrc = g_emb + (size_t)qg * 128 * DIM;
#pragma unroll
            for (int j = 0; j < 8; j++) {
                int f = tid + j * 256, r = f >> 4, c8 = f & 15;
                *(uint4*)(sQ + r * DSTR + c8 * 8) =
                    *(const uint4*)(qsrc + (size_t)r * DIM + c8 * 8);
            }
        }

        for (int j = 0; j < n; j++) {
            cp_wait<0>();      // tile j's group complete
            __syncthreads();   // S1: tile j + Q visible to all

            if (j >= 1 && tid < 128) {   // finalize unit j-1 from red
                const int qb = tid >> 5, row = tid & 31;
                const float* rb = red + ((j - 1) & 1) * 256;
                float v = fmaxf(rb[(qb * 2) * 32 + row],
                                rb[(qb * 2 + 1) * 32 + row]);
#pragma unroll
                for (int off = 16; off >= 1; off >>= 1)
                    v += __shfl_xor_sync(0xffffffffu, v, off);
                if (lane == 0)
                    out[(size_t)(qb0 + qb) * 128 + (db_base + j - 1)] = v;
            }

            float* rw = red + (j & 1) * 256 + warp * 32;
            float hm[2][2];
#pragma unroll
            for (int h = 0; h < 2; h++) {
                float acc[2][4][4];
#pragma unroll
                for (int mt = 0; mt < 2; mt++)
#pragma unroll
                    for (int nt = 0; nt < 4; nt++)
#pragma unroll
                        for (int r = 0; r < 4; r++) acc[mt][nt][r] = 0.f;

#pragma unroll
                for (int ks = 0; ks < 8; ks++) {
                    uint32_t a0[4], a1[4], b0[4], b1[4];
                    ldsm4(a0[0], a0[1], a0[2], a0[3], aoff[0] + ks * 32);
                    ldsm4(a1[0], a1[1], a1[2], a1[3], aoff[1] + ks * 32);
                    ldsm4(b0[0], b0[1], b0[2], b0[3], boff[h][0] + ks * 32);
                    ldsm4(b1[0], b1[1], b1[2], b1[3], boff[h][1] + ks * 32);
                    mma16816(acc[0][0], a0, b0[0], b0[1]);
                    mma16816(acc[0][1], a0, b0[2], b0[3]);
                    mma16816(acc[0][2], a0, b1[0], b1[1]);
                    mma16816(acc[0][3], a0, b1[2], b1[3]);
                    mma16816(acc[1][0], a1, b0[0], b0[1]);
                    mma16816(acc[1][1], a1, b0[2], b0[3]);
                    mma16816(acc[1][2], a1, b1[0], b1[1]);
                    mma16816(acc[1][3], a1, b1[2], b1[3]);
                }

                // per-pass row max; combine across passes on h==1
#pragma unroll
                for (int mt = 0; mt < 2; mt++) {
#pragma unroll
                    for (int rh = 0; rh < 2; rh++) {
                        float m = -3.4e38f;
#pragma unroll
                        for (int nt = 0; nt < 4; nt++)
                            m = fmaxf(m, fmaxf(acc[mt][nt][2 * rh],
                                               acc[mt][nt][2 * rh + 1]));
                        if (h == 0) {
                            hm[mt][rh] = m;
                        } else {
                            m = fmaxf(m, hm[mt][rh]);
                            m = fmaxf(m, __shfl_xor_sync(0xffffffffu, m, 1));
                            m = fmaxf(m, __shfl_xor_sync(0xffffffffu, m, 2));
                            if ((lane & 3) == 0)
                                rw[mt * 16 + rh * 8 + (lane >> 2)] = m;
                        }
                    }
                }
            }
            __syncthreads();   // S2: all reads of sD (and red writes) done

            if (j + 1 < n) {   // prefetch next tile into the single buffer
                const __nv_bfloat16* dsrc =
                    g_emb + (size_t)(N_QTOK + (db_base + j + 1) * 128) * DIM;
#pragma unroll
                for (int t = 0; t < 8; t++) {
                    int f = tid + t * 256, r = f >> 4, c8 = f & 15;
                    cp_async16(uD + (unsigned)(r * DSTR + c8 * 8) * 2,
                               dsrc + (size_t)r * DIM + c8 * 8);
                }
                cp_commit();
            }
        }

        // tail: finalize last unit (red written before last S2 -> visible)
        if (tid < 128) {
            const int qb = tid >> 5, row = tid & 31;
            const float* rb = red + ((n - 1) & 1) * 256;
            float v = fmaxf(rb[(qb * 2) * 32 + row],
                            rb[(qb * 2 + 1) * 32 + row]);
#pragma unroll
            for (int off = 16; off >= 1; off >>= 1)
                v += __shfl_xor_sync(0xffffffffu, v, off);
            if (lane == 0)
                out[(size_t)(qb0 + qb) * 128 + (db_base + n - 1)] = v;
        }
        __syncthreads();   // tail reads done before next segment reuses smem
        s = seg_e;
    }
}

// ---------------------------------------------------------------------------
extern "C" void kernel_launch(void* const* d_in, const int* in_sizes, int n_in,
                              void* d_out, int out_size) {
    const float* qh   = (const float*)d_in[0];
    const float* dh   = (const float*)d_in[1];
    const float* W    = (const float*)d_in[2];
    const float* bias = (const float*)d_in[3];
    float* out = (float*)d_out;

    int sms = 148;
    cudaDeviceGetAttribute(&sms, cudaDevAttrMultiProcessorCount, 0);

    const int ESMEM = 2 * BUF_ELEM * 2 + 64 * 4 * 4 + 16;  // ~107.5KB
    const int SSMEM = 2 * 128 * DSTR * 2 + 2 * 256 * 4;    // 71680
    cudaFuncSetAttribute(embed_kernel,
                         cudaFuncAttributeMaxDynamicSharedMemorySize, ESMEM);
    cudaFuncSetAttribute(sim_kernel,
                         cudaFuncAttributeMaxDynamicSharedMemorySize, SSMEM);

    embed_kernel<<<2 * sms, 256, ESMEM>>>(qh, dh, W, bias);
    sim_kernel<<<3 * sms, 256, SSMEM>>>(out);
}

// round 15
// speedup vs baseline: 1.2709x; 1.2709x over previous
#include <cuda_runtime.h>
#include <cuda_bf16.h>
#include <cstdint>
#include <cstddef>

#define N_QTOK 4096      // 128 query batches * 32 tokens
#define N_DTOK 16384     // 128 doc batches * 128 tokens
#define N_TOK  20480
#define DIM    128
#define HID    256
#define N_ETILE 320      // 20480 / 64 rows per embed tile

// bf16 normalized embeddings: rows 0..4095 = query tokens, 4096..20479 = doc
__device__ __align__(16) __nv_bfloat16 g_emb[(size_t)N_TOK * DIM];

// ---------------------------------------------------------------------------
// PTX helpers (base sm_103 only — tcgen05 needs compute_103a virtual arch,
// which the harness does not use)
// ---------------------------------------------------------------------------
__device__ __forceinline__ void ldsm4(uint32_t& r0, uint32_t& r1,
                                      uint32_t& r2, uint32_t& r3, unsigned addr) {
    asm volatile("ldmatrix.sync.aligned.m8n8.x4.shared.b16 {%0,%1,%2,%3}, [%4];\n"
                 : "=r"(r0), "=r"(r1), "=r"(r2), "=r"(r3) : "r"(addr));
}
__device__ __forceinline__ void ldsm4t(uint32_t& r0, uint32_t& r1,
                                       uint32_t& r2, uint32_t& r3, unsigned addr) {
    asm volatile("ldmatrix.sync.aligned.m8n8.x4.trans.shared.b16 {%0,%1,%2,%3}, [%4];\n"
                 : "=r"(r0), "=r"(r1), "=r"(r2), "=r"(r3) : "r"(addr));
}
__device__ __forceinline__ void mma16816(float* c, const uint32_t* a,
                                         uint32_t b0, uint32_t b1) {
    asm volatile(
        "mma.sync.aligned.m16n8k16.row.col.f32.bf16.bf16.f32 "
        "{%0,%1,%2,%3}, {%4,%5,%6,%7}, {%8,%9}, {%0,%1,%2,%3};\n"
        : "+f"(c[0]), "+f"(c[1]), "+f"(c[2]), "+f"(c[3])
        : "r"(a[0]), "r"(a[1]), "r"(a[2]), "r"(a[3]), "r"(b0), "r"(b1));
}
__device__ __forceinline__ void cp_async16(unsigned saddr, const void* g) {
    asm volatile("cp.async.cg.shared.global [%0], [%1], 16;\n"
                 :: "r"(saddr), "l"(g) : "memory");
}
__device__ __forceinline__ void cp_commit() {
    asm volatile("cp.async.commit_group;\n" ::: "memory");
}
template <int N> __device__ __forceinline__ void cp_wait() {
    asm volatile("cp.async.wait_group %0;\n" :: "n"(N) : "memory");
}
__device__ __forceinline__ uint32_t smem_u32(const void* p) {
    uint32_t a;
    asm("{ .reg .u64 t; cvta.to.shared.u64 t, %1; cvt.u32.u64 %0, t; }"
        : "=r"(a) : "l"(p));
    return a;
}
__device__ __forceinline__ void cvt_hilo4(const float4& v,
                                          __nv_bfloat16* h, __nv_bfloat16* l) {
    float vv[4] = { v.x, v.y, v.z, v.w };
#pragma unroll
    for (int e = 0; e < 4; e++) {
        h[e] = __float2bfloat16(vv[e]);
        l[e] = __float2bfloat16(vv[e] - __bfloat162float(h[e]));
    }
}

// ---------------------------------------------------------------------------
// Kernel 1: projection + bias + L2 normalize (hi/lo bf16 split ~ fp32).
// SINGLE-WAVE: grid = 320 CTAs, one 64-row tile per CTA (blockIdx-indexed),
// occ 3 (single-buffered smem ~54KB) -> every tile resident in wave 1.
// Block 256 thr / 8 warps as 2(M) x 4(N): warp tile 32 rows x 32 cols.
// Per-kc: convert W chunk + A chunk fp32 -> hi/lo bf16 smem (bulk-sync).
// ---------------------------------------------------------------------------
#define AK 72       // A smem k-stride (144B pitch, conflict-free)
#define WP 136      // W smem n-stride (272B pitch, conflict-free)

__global__ __launch_bounds__(256, 3) void embed_kernel(
    const float* __restrict__ qh, const float* __restrict__ dh,
    const float* __restrict__ W, const float* __restrict__ bias)
{
    extern __shared__ char esm[];
    __nv_bfloat16* sWhi = (__nv_bfloat16*)esm;            // 64 x 136
    __nv_bfloat16* sWlo = sWhi + 64 * WP;
    __nv_bfloat16* sAhi = sWlo + 64 * WP;                 // 64 x 72
    __nv_bfloat16* sAlo = sAhi + 64 * AK;
    float* ssp = (float*)(sAlo + 64 * AK);                // [64][4]

    const int tid  = threadIdx.x;
    const int lane = tid & 31, warp = tid >> 5;
    const int wm = warp >> 2, wn = warp & 3;

    const unsigned uWhi = smem_u32(sWhi);
    const unsigned uWlo = smem_u32(sWlo);
    const unsigned uAhi = smem_u32(sAhi);
    const unsigned uAlo = smem_u32(sAlo);

    unsigned aoff[2];
#pragma unroll
    for (int mt = 0; mt < 2; mt++)
        aoff[mt] = (unsigned)((wm * 32 + mt * 16 + (lane & 15)) * AK
                              + (lane >> 4) * 8) * 2;
    const int bk = (lane & 7) + ((lane >> 3) & 1) * 8;
    const unsigned bnb = (unsigned)(wn * 32 + (lane >> 4) * 8) * 2;
    const int cbase = (lane & 3) * 2;

    const int row0 = blockIdx.x * 64;
    const float* src = (row0 < N_QTOK)
        ? (qh + (size_t)row0 * HID)
        : (dh + (size_t)(row0 - N_QTOK) * HID);

    float acc[2][4][4];
#pragma unroll
    for (int mt = 0; mt < 2; mt++)
#pragma unroll
        for (int nt = 0; nt < 4; nt++)
#pragma unroll
            for (int r = 0; r < 4; r++) acc[mt][nt][r] = 0.f;

    for (int kc = 0; kc < 4; kc++) {
        const int k0 = kc * 64;
        if (kc) __syncthreads();   // prior kc ldsm reads done

        // W chunk: 64 k x 128 n fp32 -> hi/lo (8 float4 / thread)
#pragma unroll
        for (int j = 0; j < 8; j++) {
            int f = tid + j * 256, r = f >> 5, c4 = f & 31;
            float4 v = *(const float4*)(W + (size_t)(k0 + r) * DIM + c4 * 4);
            __nv_bfloat16 h[4], l[4];
            cvt_hilo4(v, h, l);
            *(uint2*)&sWhi[r * WP + c4 * 4] = *(uint2*)h;
            *(uint2*)&sWlo[r * WP + c4 * 4] = *(uint2*)l;
        }
        // A chunk: 64 rows x 64 k fp32 -> hi/lo (4 float4 / thread)
#pragma unroll
        for (int j = 0; j < 4; j++) {
            int f = tid + j * 256, r = f >> 4, cv = f & 15;
            float4 v = *(const float4*)(src + (size_t)r * HID + k0 + cv * 4);
            __nv_bfloat16 h[4], l[4];
            cvt_hilo4(v, h, l);
            *(uint2*)&sAhi[r * AK + cv * 4] = *(uint2*)h;
            *(uint2*)&sAlo[r * AK + cv * 4] = *(uint2*)l;
        }
        __syncthreads();

#pragma unroll
        for (int ks = 0; ks < 4; ks++) {
            uint32_t ah0[4], ah1[4], al0[4], al1[4];
            ldsm4(ah0[0], ah0[1], ah0[2], ah0[3], uAhi + aoff[0] + ks * 32);
            ldsm4(ah1[0], ah1[1], ah1[2], ah1[3], uAhi + aoff[1] + ks * 32);
            ldsm4(al0[0], al0[1], al0[2], al0[3], uAlo + aoff[0] + ks * 32);
            ldsm4(al1[0], al1[1], al1[2], al1[3], uAlo + aoff[1] + ks * 32);
            const unsigned be = (unsigned)((ks * 16 + bk) * WP) * 2 + bnb;
            uint32_t bh0[4], bh1[4], bl0[4], bl1[4];
            ldsm4t(bh0[0], bh0[1], bh0[2], bh0[3], uWhi + be);
            ldsm4t(bh1[0], bh1[1], bh1[2], bh1[3], uWhi + be + 32);
            ldsm4t(bl0[0], bl0[1], bl0[2], bl0[3], uWlo + be);
            ldsm4t(bl1[0], bl1[1], bl1[2], bl1[3], uWlo + be + 32);

            mma16816(acc[0][0], ah0, bh0[0], bh0[1]);
            mma16816(acc[0][0], ah0, bl0[0], bl0[1]);
            mma16816(acc[0][0], al0, bh0[0], bh0[1]);
            mma16816(acc[0][1], ah0, bh0[2], bh0[3]);
            mma16816(acc[0][1], ah0, bl0[2], bl0[3]);
            mma16816(acc[0][1], al0, bh0[2], bh0[3]);
            mma16816(acc[0][2], ah0, bh1[0], bh1[1]);
            mma16816(acc[0][2], ah0, bl1[0], bl1[1]);
            mma16816(acc[0][2], al0, bh1[0], bh1[1]);
            mma16816(acc[0][3], ah0, bh1[2], bh1[3]);
            mma16816(acc[0][3], ah0, bl1[2], bl1[3]);
            mma16816(acc[0][3], al0, bh1[2], bh1[3]);

            mma16816(acc[1][0], ah1, bh0[0], bh0[1]);
            mma16816(acc[1][0], ah1, bl0[0], bl0[1]);
            mma16816(acc[1][0], al1, bh0[0], bh0[1]);
            mma16816(acc[1][1], ah1, bh0[2], bh0[3]);
            mma16816(acc[1][1], ah1, bl0[2], bl0[3]);
            mma16816(acc[1][1], al1, bh0[2], bh0[3]);
            mma16816(acc[1][2], ah1, bh1[0], bh1[1]);
            mma16816(acc[1][2], ah1, bl1[0], bl1[1]);
            mma16816(acc[1][2], al1, bh1[0], bh1[1]);
            mma16816(acc[1][3], ah1, bh1[2], bh1[3]);
            mma16816(acc[1][3], ah1, bl1[2], bl1[3]);
            mma16816(acc[1][3], al1, bh1[2], bh1[3]);
        }
    }

    // epilogue: bias + partial sum-of-squares over this warp's 32 cols
#pragma unroll
    for (int mt = 0; mt < 2; mt++) {
        float s0 = 0.f, s1 = 0.f;
#pragma unroll
        for (int nt = 0; nt < 4; nt++) {
            float2 bv = *(const float2*)(bias + wn * 32 + nt * 8 + cbase);
            acc[mt][nt][0] += bv.x; acc[mt][nt][1] += bv.y;
            acc[mt][nt][2] += bv.x; acc[mt][nt][3] += bv.y;
            s0 += acc[mt][nt][0] * acc[mt][nt][0]
                + acc[mt][nt][1] * acc[mt][nt][1];
            s1 += acc[mt][nt][2] * acc[mt][nt][2]
                + acc[mt][nt][3] * acc[mt][nt][3];
        }
        s0 += __shfl_xor_sync(0xffffffffu, s0, 1);
        s0 += __shfl_xor_sync(0xffffffffu, s0, 2);
        s1 += __shfl_xor_sync(0xffffffffu, s1, 1);
        s1 += __shfl_xor_sync(0xffffffffu, s1, 2);
        if ((lane & 3) == 0) {
            ssp[(wm * 32 + mt * 16 + (lane >> 2)) * 4 + wn] = s0;
            ssp[(wm * 32 + mt * 16 + 8 + (lane >> 2)) * 4 + wn] = s1;
        }
    }
    __syncthreads();
#pragma unroll
    for (int mt = 0; mt < 2; mt++) {
        const int r0 = wm * 32 + mt * 16 + (lane >> 2);
        const int r1 = r0 + 8;
        float ss0 = ssp[r0 * 4] + ssp[r0 * 4 + 1]
                  + ssp[r0 * 4 + 2] + ssp[r0 * 4 + 3];
        float ss1 = ssp[r1 * 4] + ssp[r1 * 4 + 1]
                  + ssp[r1 * 4 + 2] + ssp[r1 * 4 + 3];
        float inv0 = 1.f / fmaxf(sqrtf(ss0), 1e-12f);
        float inv1 = 1.f / fmaxf(sqrtf(ss1), 1e-12f);
#pragma unroll
        for (int nt = 0; nt < 4; nt++) {
            __nv_bfloat162 vA, vB;
            vA.x = __float2bfloat16(acc[mt][nt][0] * inv0);
            vA.y = __float2bfloat16(acc[mt][nt][1] * inv0);
            vB.x = __float2bfloat16(acc[mt][nt][2] * inv1);
            vB.y = __float2bfloat16(acc[mt][nt][3] * inv1);
            *(__nv_bfloat162*)(g_emb + (size_t)(row0 + r0) * DIM
                               + wn * 32 + nt * 8 + cbase) = vA;
            *(__nv_bfloat162*)(g_emb + (size_t)(row0 + r1) * DIM
                               + wn * 32 + nt * 8 + cbase) = vB;
        }
    }
}

// ---------------------------------------------------------------------------
// Kernel 2: PERSISTENT fused similarity GEMM + max_t + sum_s.
// Proven best form (R11, 46.9us): occ 2, double-buffered doc tiles, full
// N=128 mainloop (6 ldsm : 16 mma per ks), 2 barriers/tile.
// ---------------------------------------------------------------------------
#define DSTR 136

__global__ __launch_bounds__(256, 2) void sim_kernel(float* __restrict__ out)
{
    extern __shared__ char smem[];
    __nv_bfloat16* sQ = (__nv_bfloat16*)smem;              // 128 x 136
    __nv_bfloat16* sD = sQ + 128 * DSTR;                   // 2 x (128 x 136)
    float* red = (float*)(sD + 2 * 128 * DSTR);            // [2][8 warps][32]

    const int tid  = threadIdx.x;
    const int lane = tid & 31, warp = tid >> 5;
    const int wm = warp >> 1, wn = warp & 1;
    const unsigned G = gridDim.x, c = blockIdx.x;
    unsigned s = (4096u * c) / G;
    const unsigned e = (4096u * (c + 1)) / G;

    const unsigned uQ = smem_u32(sQ);
    const unsigned uD = smem_u32(sD);

    unsigned aoff[2];
#pragma unroll
    for (int mt = 0; mt < 2; mt++) {
        int row = wm * 32 + mt * 16 + (lane & 15);
        int col = (lane >> 4) * 8;
        aoff[mt] = uQ + (unsigned)(row * DSTR + col) * 2;
    }
    unsigned boff[4];
#pragma unroll
    for (int g = 0; g < 4; g++) {
        int row = wn * 64 + g * 16 + (lane & 7) + (lane >> 4) * 8;
        int col = ((lane >> 3) & 1) * 8;
        boff[g] = (unsigned)(row * DSTR + col) * 2;
    }

    while (s < e) {
        const unsigned qg = s >> 7;
        const unsigned seg_e = min(e, (qg + 1) << 7);
        const int n = (int)(seg_e - s);
        const unsigned qb0 = qg * 4;
        const unsigned db_base = s & 127;

        {   // load Q tile for this segment
            const __nv_bfloat16* qsrc = g_emb + (size_t)qg * 128 * DIM;
#pragma unroll
            for (int j = 0; j < 8; j++) {
                int f = tid + j * 256, r = f >> 4, c8 = f & 15;
                *(uint4*)(sQ + r * DSTR + c8 * 8) =
                    *(const uint4*)(qsrc + (size_t)r * DIM + c8 * 8);
            }
        }
        {   // prefetch first doc tile of segment into buffer 0
            const __nv_bfloat16* dsrc =
                g_emb + (size_t)(N_QTOK + db_base * 128) * DIM;
#pragma unroll
            for (int j = 0; j < 8; j++) {
                int f = tid + j * 256, r = f >> 4, c8 = f & 15;
                cp_async16(uD + (unsigned)(r * DSTR + c8 * 8) * 2,
                           dsrc + (size_t)r * DIM + c8 * 8);
            }
            cp_commit();
        }

        for (int j = 0; j < n; j++) {
            if (j + 1 < n) {
                const __nv_bfloat16* dsrc =
                    g_emb + (size_t)(N_QTOK + (db_base + j + 1) * 128) * DIM;
                const unsigned dst =
                    uD + (unsigned)((j + 1) & 1) * (128 * DSTR * 2);
#pragma unroll
                for (int t = 0; t < 8; t++) {
                    int f = tid + t * 256, r = f >> 4, c8 = f & 15;
                    cp_async16(dst + (unsigned)(r * DSTR + c8 * 8) * 2,
                               dsrc + (size_t)r * DIM + c8 * 8);
                }
                cp_commit();
                cp_wait<1>();
            } else {
                cp_wait<0>();
            }
            __syncthreads();   // S1: tile j data + Q visible

            if (j >= 1 && tid < 128) {   // finalize unit j-1
                const int qb = tid >> 5, row = tid & 31;
                const float* rb = red + ((j - 1) & 1) * 256;
                float v = fmaxf(rb[(qb * 2) * 32 + row],
                                rb[(qb * 2 + 1) * 32 + row]);
#pragma unroll
                for (int off = 16; off >= 1; off >>= 1)
                    v += __shfl_xor_sync(0xffffffffu, v, off);
                if (lane == 0)
                    out[(size_t)(qb0 + qb) * 128 + (db_base + j - 1)] = v;
            }

            float acc[2][8][4];
#pragma unroll
            for (int mt = 0; mt < 2; mt++)
#pragma unroll
                for (int t = 0; t < 8; t++)
#pragma unroll
                    for (int r = 0; r < 4; r++) acc[mt][t][r] = 0.f;

            const unsigned dbase = uD + (unsigned)(j & 1) * (128 * DSTR * 2);
#pragma unroll
            for (int ks = 0; ks < 8; ks++) {
                uint32_t a[2][4], b[4][4];
                ldsm4(a[0][0], a[0][1], a[0][2], a[0][3], aoff[0] + ks * 32);
                ldsm4(a[1][0], a[1][1], a[1][2], a[1][3], aoff[1] + ks * 32);
#pragma unroll
                for (int g = 0; g < 4; g++)
                    ldsm4(b[g][0], b[g][1], b[g][2], b[g][3],
                          dbase + boff[g] + ks * 32);
#pragma unroll
                for (int mt = 0; mt < 2; mt++)
#pragma unroll
                    for (int t = 0; t < 8; t++)
                        mma16816(acc[mt][t], a[mt],
                                 b[t >> 1][(t & 1) * 2],
                                 b[t >> 1][(t & 1) * 2 + 1]);
            }

            // in-warp row-max over this warp's 64 columns -> red[j&1]
            float* rw = red + (j & 1) * 256 + warp * 32;
#pragma unroll
            for (int mt = 0; mt < 2; mt++) {
#pragma unroll
                for (int h = 0; h < 2; h++) {
                    float m = -3.4e38f;
#pragma unroll
                    for (int t = 0; t < 8; t++)
                        m = fmaxf(m, fmaxf(acc[mt][t][2 * h],
                                           acc[mt][t][2 * h + 1]));
                    m = fmaxf(m, __shfl_xor_sync(0xffffffffu, m, 1));
                    m = fmaxf(m, __shfl_xor_sync(0xffffffffu, m, 2));
                    if ((lane & 3) == 0)
                        rw[mt * 16 + h * 8 + (lane >> 2)] = m;
                }
            }
            __syncthreads();   // S2: red complete; buffers reusable
        }

        // tail: finalize last unit of segment
        if (tid < 128) {
            const int qb = tid >> 5, row = tid & 31;
            const float* rb = red + ((n - 1) & 1) * 256;
            float v = fmaxf(rb[(qb * 2) * 32 + row],
                            rb[(qb * 2 + 1) * 32 + row]);
#pragma unroll
            for (int off = 16; off >= 1; off >>= 1)
                v += __shfl_xor_sync(0xffffffffu, v, off);
            if (lane == 0)
                out[(size_t)(qb0 + qb) * 128 + (db_base + n - 1)] = v;
        }
        __syncthreads();
        s = seg_e;
    }
}

// ---------------------------------------------------------------------------
extern "C" void kernel_launch(void* const* d_in, const int* in_sizes, int n_in,
                              void* d_out, int out_size) {
    const float* qh   = (const float*)d_in[0];
    const float* dh   = (const float*)d_in[1];
    const float* W    = (const float*)d_in[2];
    const float* bias = (const float*)d_in[3];
    float* out = (float*)d_out;

    int sms = 148;
    cudaDeviceGetAttribute(&sms, cudaDevAttrMultiProcessorCount, 0);

    const int ESMEM = 2 * (64 * WP * 2) + 2 * (64 * AK * 2) + 64 * 4 * 4;
    // = 34816 + 18432 + 1024 = 54272 -> occ 3
    const int SSMEM = 3 * 128 * DSTR * 2 + 2 * 256 * 4;   // 106496 -> occ 2
    cudaFuncSetAttribute(embed_kernel,
                         cudaFuncAttributeMaxDynamicSharedMemorySize, ESMEM);
    cudaFuncSetAttribute(sim_kernel,
                         cudaFuncAttributeMaxDynamicSharedMemorySize, SSMEM);

    embed_kernel<<<N_ETILE, 256, ESMEM>>>(qh, dh, W, bias);
    sim_kernel<<<2 * sms, 256, SSMEM>>>(out);
}

// round 16
// speedup vs baseline: 1.4510x; 1.1418x over previous
#include <cuda_runtime.h>
#include <cuda_fp16.h>
#include <cstdint>
#include <cstddef>

#define N_QTOK 4096      // 128 query batches * 32 tokens
#define N_DTOK 16384     // 128 doc batches * 128 tokens
#define N_TOK  20480
#define DIM    128
#define HID    256
#define N_ETILE 320      // 20480 / 64 rows per embed tile

// fp16 normalized embeddings: rows 0..4095 = query tokens, 4096..20479 = doc
__device__ __align__(16) __half g_emb[(size_t)N_TOK * DIM];

// ---------------------------------------------------------------------------
// PTX helpers (base sm_103 only — tcgen05 needs compute_103a virtual arch,
// which the harness does not use)
// ---------------------------------------------------------------------------
__device__ __forceinline__ void ldsm4(uint32_t& r0, uint32_t& r1,
                                      uint32_t& r2, uint32_t& r3, unsigned addr) {
    asm volatile("ldmatrix.sync.aligned.m8n8.x4.shared.b16 {%0,%1,%2,%3}, [%4];\n"
                 : "=r"(r0), "=r"(r1), "=r"(r2), "=r"(r3) : "r"(addr));
}
__device__ __forceinline__ void ldsm4t(uint32_t& r0, uint32_t& r1,
                                       uint32_t& r2, uint32_t& r3, unsigned addr) {
    asm volatile("ldmatrix.sync.aligned.m8n8.x4.trans.shared.b16 {%0,%1,%2,%3}, [%4];\n"
                 : "=r"(r0), "=r"(r1), "=r"(r2), "=r"(r3) : "r"(addr));
}
// fp16 operands, fp32 accumulate
__device__ __forceinline__ void mma16816h(float* c, const uint32_t* a,
                                          uint32_t b0, uint32_t b1) {
    asm volatile(
        "mma.sync.aligned.m16n8k16.row.col.f32.f16.f16.f32 "
        "{%0,%1,%2,%3}, {%4,%5,%6,%7}, {%8,%9}, {%0,%1,%2,%3};\n"
        : "+f"(c[0]), "+f"(c[1]), "+f"(c[2]), "+f"(c[3])
        : "r"(a[0]), "r"(a[1]), "r"(a[2]), "r"(a[3]), "r"(b0), "r"(b1));
}
__device__ __forceinline__ void cp_async16(unsigned saddr, const void* g) {
    asm volatile("cp.async.cg.shared.global [%0], [%1], 16;\n"
                 :: "r"(saddr), "l"(g) : "memory");
}
__device__ __forceinline__ void cp_commit() {
    asm volatile("cp.async.commit_group;\n" ::: "memory");
}
template <int N> __device__ __forceinline__ void cp_wait() {
    asm volatile("cp.async.wait_group %0;\n" :: "n"(N) : "memory");
}
__device__ __forceinline__ uint32_t smem_u32(const void* p) {
    uint32_t a;
    asm("{ .reg .u64 t; cvta.to.shared.u64 t, %1; cvt.u32.u64 %0, t; }"
        : "=r"(a) : "l"(p));
    return a;
}

// ---------------------------------------------------------------------------
// Kernel 1: projection + bias + L2 normalize, SINGLE-PASS fp16.
// grid = 320 CTAs (one 64-row tile each, blockIdx-indexed); smem ~27.7KB ->
// occ 3+ -> entire grid resident in wave 1.
// Block 256 thr / 8 warps as 2(M) x 4(N): warp tile 32 rows x 32 cols.
// Per-kc: convert W chunk + A chunk fp32 -> fp16 smem, then 4 k16 mma steps.
// fp32 accumulators; fp16 storage of normalized embeddings (2^-11 quant).
// ---------------------------------------------------------------------------
#define AK 72       // A smem k-stride (144B pitch, conflict-free)
#define WP 136      // W smem n-stride (272B pitch, conflict-free)

__global__ __launch_bounds__(256, 3) void embed_kernel(
    const float* __restrict__ qh, const float* __restrict__ dh,
    const float* __restrict__ W, const float* __restrict__ bias)
{
    extern __shared__ char esm[];
    __half* sW = (__half*)esm;                  // 64 x 136
    __half* sA = sW + 64 * WP;                  // 64 x 72
    float* ssp = (float*)(sA + 64 * AK);        // [64][4]

    const int tid  = threadIdx.x;
    const int lane = tid & 31, warp = tid >> 5;
    const int wm = warp >> 2, wn = warp & 3;

    const unsigned uW = smem_u32(sW);
    const unsigned uA = smem_u32(sA);

    unsigned aoff[2];
#pragma unroll
    for (int mt = 0; mt < 2; mt++)
        aoff[mt] = (unsigned)((wm * 32 + mt * 16 + (lane & 15)) * AK
                              + (lane >> 4) * 8) * 2;
    const int bk = (lane & 7) + ((lane >> 3) & 1) * 8;
    const unsigned bnb = (unsigned)(wn * 32 + (lane >> 4) * 8) * 2;
    const int cbase = (lane & 3) * 2;

    const int row0 = blockIdx.x * 64;
    const float* src = (row0 < N_QTOK)
        ? (qh + (size_t)row0 * HID)
        : (dh + (size_t)(row0 - N_QTOK) * HID);

    float acc[2][4][4];
#pragma unroll
    for (int mt = 0; mt < 2; mt++)
#pragma unroll
        for (int nt = 0; nt < 4; nt++)
#pragma unroll
            for (int r = 0; r < 4; r++) acc[mt][nt][r] = 0.f;

    for (int kc = 0; kc < 4; kc++) {
        const int k0 = kc * 64;
        if (kc) __syncthreads();   // prior kc ldsm reads done

        // W chunk: 64 k x 128 n fp32 -> fp16 (8 float4 / thread)
#pragma unroll
        for (int j = 0; j < 8; j++) {
            int f = tid + j * 256, r = f >> 5, c4 = f & 31;
            float4 v = *(const float4*)(W + (size_t)(k0 + r) * DIM + c4 * 4);
            __half2 h0 = __float22half2_rn(make_float2(v.x, v.y));
            __half2 h1 = __float22half2_rn(make_float2(v.z, v.w));
            *(__half2*)&sW[r * WP + c4 * 4]     = h0;
            *(__half2*)&sW[r * WP + c4 * 4 + 2] = h1;
        }
        // A chunk: 64 rows x 64 k fp32 -> fp16 (4 float4 / thread)
#pragma unroll
        for (int j = 0; j < 4; j++) {
            int f = tid + j * 256, r = f >> 4, cv = f & 15;
            float4 v = *(const float4*)(src + (size_t)r * HID + k0 + cv * 4);
            __half2 h0 = __float22half2_rn(make_float2(v.x, v.y));
            __half2 h1 = __float22half2_rn(make_float2(v.z, v.w));
            *(__half2*)&sA[r * AK + cv * 4]     = h0;
            *(__half2*)&sA[r * AK + cv * 4 + 2] = h1;
        }
        __syncthreads();

#pragma unroll
        for (int ks = 0; ks < 4; ks++) {
            uint32_t a0[4], a1[4];
            ldsm4(a0[0], a0[1], a0[2], a0[3], uA + aoff[0] + ks * 32);
            ldsm4(a1[0], a1[1], a1[2], a1[3], uA + aoff[1] + ks * 32);
            const unsigned be = (unsigned)((ks * 16 + bk) * WP) * 2 + bnb;
            uint32_t b0[4], b1[4];
            ldsm4t(b0[0], b0[1], b0[2], b0[3], uW + be);
            ldsm4t(b1[0], b1[1], b1[2], b1[3], uW + be + 32);

            mma16816h(acc[0][0], a0, b0[0], b0[1]);
            mma16816h(acc[0][1], a0, b0[2], b0[3]);
            mma16816h(acc[0][2], a0, b1[0], b1[1]);
            mma16816h(acc[0][3], a0, b1[2], b1[3]);
            mma16816h(acc[1][0], a1, b0[0], b0[1]);
            mma16816h(acc[1][1], a1, b0[2], b0[3]);
            mma16816h(acc[1][2], a1, b1[0], b1[1]);
            mma16816h(acc[1][3], a1, b1[2], b1[3]);
        }
    }

    // epilogue: bias + partial sum-of-squares over this warp's 32 cols
#pragma unroll
    for (int mt = 0; mt < 2; mt++) {
        float s0 = 0.f, s1 = 0.f;
#pragma unroll
        for (int nt = 0; nt < 4; nt++) {
            float2 bv = *(const float2*)(bias + wn * 32 + nt * 8 + cbase);
            acc[mt][nt][0] += bv.x; acc[mt][nt][1] += bv.y;
            acc[mt][nt][2] += bv.x; acc[mt][nt][3] += bv.y;
            s0 += acc[mt][nt][0] * acc[mt][nt][0]
                + acc[mt][nt][1] * acc[mt][nt][1];
            s1 += acc[mt][nt][2] * acc[mt][nt][2]
                + acc[mt][nt][3] * acc[mt][nt][3];
        }
        s0 += __shfl_xor_sync(0xffffffffu, s0, 1);
        s0 += __shfl_xor_sync(0xffffffffu, s0, 2);
        s1 += __shfl_xor_sync(0xffffffffu, s1, 1);
        s1 += __shfl_xor_sync(0xffffffffu, s1, 2);
        if ((lane & 3) == 0) {
            ssp[(wm * 32 + mt * 16 + (lane >> 2)) * 4 + wn] = s0;
            ssp[(wm * 32 + mt * 16 + 8 + (lane >> 2)) * 4 + wn] = s1;
        }
    }
    __syncthreads();
#pragma unroll
    for (int mt = 0; mt < 2; mt++) {
        const int r0 = wm * 32 + mt * 16 + (lane >> 2);
        const int r1 = r0 + 8;
        float ss0 = ssp[r0 * 4] + ssp[r0 * 4 + 1]
                  + ssp[r0 * 4 + 2] + ssp[r0 * 4 + 3];
        float ss1 = ssp[r1 * 4] + ssp[r1 * 4 + 1]
                  + ssp[r1 * 4 + 2] + ssp[r1 * 4 + 3];
        float inv0 = 1.f / fmaxf(sqrtf(ss0), 1e-12f);
        float inv1 = 1.f / fmaxf(sqrtf(ss1), 1e-12f);
#pragma unroll
        for (int nt = 0; nt < 4; nt++) {
            __half2 vA = __float22half2_rn(
                make_float2(acc[mt][nt][0] * inv0, acc[mt][nt][1] * inv0));
            __half2 vB = __float22half2_rn(
                make_float2(acc[mt][nt][2] * inv1, acc[mt][nt][3] * inv1));
            *(__half2*)(g_emb + (size_t)(row0 + r0) * DIM
                        + wn * 32 + nt * 8 + cbase) = vA;
            *(__half2*)(g_emb + (size_t)(row0 + r1) * DIM
                        + wn * 32 + nt * 8 + cbase) = vB;
        }
    }
}

// ---------------------------------------------------------------------------
// Kernel 2: PERSISTENT fused similarity GEMM + max_t + sum_s.
// Proven best form (R11/R15, ~47us): occ 2, double-buffered doc tiles, full
// N=128 mainloop (6 ldsm : 16 mma per ks), 2 barriers/tile. fp16 operands.
// ---------------------------------------------------------------------------
#define DSTR 136

__global__ __launch_bounds__(256, 2) void sim_kernel(float* __restrict__ out)
{
    extern __shared__ char smem[];
    __half* sQ = (__half*)smem;                            // 128 x 136
    __half* sD = sQ + 128 * DSTR;                          // 2 x (128 x 136)
    float* red = (float*)(sD + 2 * 128 * DSTR);            // [2][8 warps][32]

    const int tid  = threadIdx.x;
    const int lane = tid & 31, warp = tid >> 5;
    const int wm = warp >> 1, wn = warp & 1;
    const unsigned G = gridDim.x, c = blockIdx.x;
    unsigned s = (4096u * c) / G;
    const unsigned e = (4096u * (c + 1)) / G;

    const unsigned uQ = smem_u32(sQ);
    const unsigned uD = smem_u32(sD);

    unsigned aoff[2];
#pragma unroll
    for (int mt = 0; mt < 2; mt++) {
        int row = wm * 32 + mt * 16 + (lane & 15);
        int col = (lane >> 4) * 8;
        aoff[mt] = uQ + (unsigned)(row * DSTR + col) * 2;
    }
    unsigned boff[4];
#pragma unroll
    for (int g = 0; g < 4; g++) {
        int row = wn * 64 + g * 16 + (lane & 7) + (lane >> 4) * 8;
        int col = ((lane >> 3) & 1) * 8;
        boff[g] = (unsigned)(row * DSTR + col) * 2;
    }

    while (s < e) {
        const unsigned qg = s >> 7;
        const unsigned seg_e = min(e, (qg + 1) << 7);
        const int n = (int)(seg_e - s);
        const unsigned qb0 = qg * 4;
        const unsigned db_base = s & 127;

        {   // load Q tile for this segment
            const __half* qsrc = g_emb + (size_t)qg * 128 * DIM;
#pragma unroll
            for (int j = 0; j < 8; j++) {
                int f = tid + j * 256, r = f >> 4, c8 = f & 15;
                *(uint4*)(sQ + r * DSTR + c8 * 8) =
                    *(const uint4*)(qsrc + (size_t)r * DIM + c8 * 8);
            }
        }
        {   // prefetch first doc tile of segment into buffer 0
            const __half* dsrc =
                g_emb + (size_t)(N_QTOK + db_base * 128) * DIM;
#pragma unroll
            for (int j = 0; j < 8; j++) {
                int f = tid + j * 256, r = f >> 4, c8 = f & 15;
                cp_async16(uD + (unsigned)(r * DSTR + c8 * 8) * 2,
                           dsrc + (size_t)r * DIM + c8 * 8);
            }
            cp_commit();
        }

        for (int j = 0; j < n; j++) {
            if (j + 1 < n) {
                const __half* dsrc =
                    g_emb + (size_t)(N_QTOK + (db_base + j + 1) * 128) * DIM;
                const unsigned dst =
                    uD + (unsigned)((j + 1) & 1) * (128 * DSTR * 2);
#pragma unroll
                for (int t = 0; t < 8; t++) {
                    int f = tid + t * 256, r = f >> 4, c8 = f & 15;
                    cp_async16(dst + (unsigned)(r * DSTR + c8 * 8) * 2,
                               dsrc + (size_t)r * DIM + c8 * 8);
                }
                cp_commit();
                cp_wait<1>();
            } else {
                cp_wait<0>();
            }
            __syncthreads();   // S1: tile j data + Q visible

            if (j >= 1 && tid < 128) {   // finalize unit j-1
                const int qb = tid >> 5, row = tid & 31;
                const float* rb = red + ((j - 1) & 1) * 256;
                float v = fmaxf(rb[(qb * 2) * 32 + row],
                                rb[(qb * 2 + 1) * 32 + row]);
#pragma unroll
                for (int off = 16; off >= 1; off >>= 1)
                    v += __shfl_xor_sync(0xffffffffu, v, off);
                if (lane == 0)
                    out[(size_t)(qb0 + qb) * 128 + (db_base + j - 1)] = v;
            }

            float acc[2][8][4];
#pragma unroll
            for (int mt = 0; mt < 2; mt++)
#pragma unroll
                for (int t = 0; t < 8; t++)
#pragma unroll
                    for (int r = 0; r < 4; r++) acc[mt][t][r] = 0.f;

            const unsigned dbase = uD + (unsigned)(j & 1) * (128 * DSTR * 2);
#pragma unroll
            for (int ks = 0; ks < 8; ks++) {
                uint32_t a[2][4], b[4][4];
                ldsm4(a[0][0], a[0][1], a[0][2], a[0][3], aoff[0] + ks * 32);
                ldsm4(a[1][0], a[1][1], a[1][2], a[1][3], aoff[1] + ks * 32);
#pragma unroll
                for (int g = 0; g < 4; g++)
                    ldsm4(b[g][0], b[g][1], b[g][2], b[g][3],
                          dbase + boff[g] + ks * 32);
#pragma unroll
                for (int mt = 0; mt < 2; mt++)
#pragma unroll
                    for (int t = 0; t < 8; t++)
                        mma16816h(acc[mt][t], a[mt],
                                  b[t >> 1][(t & 1) * 2],
                                  b[t >> 1][(t & 1) * 2 + 1]);
            }

            // in-warp row-max over this warp's 64 columns -> red[j&1]
            float* rw = red + (j & 1) * 256 + warp * 32;
#pragma unroll
            for (int mt = 0; mt < 2; mt++) {
#pragma unroll
                for (int h = 0; h < 2; h++) {
                    float m = -3.4e38f;
#pragma unroll
                    for (int t = 0; t < 8; t++)
                        m = fmaxf(m, fmaxf(acc[mt][t][2 * h],
                                           acc[mt][t][2 * h + 1]));
                    m = fmaxf(m, __shfl_xor_sync(0xffffffffu, m, 1));
                    m = fmaxf(m, __shfl_xor_sync(0xffffffffu, m, 2));
                    if ((lane & 3) == 0)
                        rw[mt * 16 + h * 8 + (lane >> 2)] = m;
                }
            }
            __syncthreads();   // S2: red complete; buffers reusable
        }

        // tail: finalize last unit of segment
        if (tid < 128) {
            const int qb = tid >> 5, row = tid & 31;
            const float* rb = red + ((n - 1) & 1) * 256;
            float v = fmaxf(rb[(qb * 2) * 32 + row],
                            rb[(qb * 2 + 1) * 32 + row]);
#pragma unroll
            for (int off = 16; off >= 1; off >>= 1)
                v += __shfl_xor_sync(0xffffffffu, v, off);
            if (lane == 0)
                out[(size_t)(qb0 + qb) * 128 + (db_base + n - 1)] = v;
        }
        __syncthreads();
        s = seg_e;
    }
}

// ---------------------------------------------------------------------------
extern "C" void kernel_launch(void* const* d_in, const int* in_sizes, int n_in,
                              void* d_out, int out_size) {
    const float* qh   = (const float*)d_in[0];
    const float* dh   = (const float*)d_in[1];
    const float* W    = (const float*)d_in[2];
    const float* bias = (const float*)d_in[3];
    float* out = (float*)d_out;

    int sms = 148;
    cudaDeviceGetAttribute(&sms, cudaDevAttrMultiProcessorCount, 0);

    const int ESMEM = 64 * WP * 2 + 64 * AK * 2 + 64 * 4 * 4;
    // = 17408 + 9216 + 1024 = 27648 -> occ 3+ (grid 320 fully resident)
    const int SSMEM = 3 * 128 * DSTR * 2 + 2 * 256 * 4;   // 106496 -> occ 2
    cudaFuncSetAttribute(embed_kernel,
                         cudaFuncAttributeMaxDynamicSharedMemorySize, ESMEM);
    cudaFuncSetAttribute(sim_kernel,
                         cudaFuncAttributeMaxDynamicSharedMemorySize, SSMEM);

    embed_kernel<<<N_ETILE, 256, ESMEM>>>(qh, dh, W, bias);
    sim_kernel<<<2 * sms, 256, SSMEM>>>(out);
}

// round 17
// speedup vs baseline: 1.5000x; 1.0337x over previous
#include <cuda_runtime.h>
#include <cuda_fp16.h>
#include <cstdint>
#include <cstddef>

#define N_QTOK 4096      // 128 query batches * 32 tokens
#define N_DTOK 16384     // 128 doc batches * 128 tokens
#define N_TOK  20480
#define DIM    128
#define HID    256
#define N_ETILE 320      // 20480 / 64 rows per embed tile

// fp16 normalized embeddings: rows 0..4095 = query tokens, 4096..20479 = doc
__device__ __align__(16) __half g_emb[(size_t)N_TOK * DIM];

// ---------------------------------------------------------------------------
// PTX helpers (base sm_103 only — tcgen05 needs compute_103a virtual arch,
// which the harness does not use)
// ---------------------------------------------------------------------------
__device__ __forceinline__ void ldsm4(uint32_t& r0, uint32_t& r1,
                                      uint32_t& r2, uint32_t& r3, unsigned addr) {
    asm volatile("ldmatrix.sync.aligned.m8n8.x4.shared.b16 {%0,%1,%2,%3}, [%4];\n"
                 : "=r"(r0), "=r"(r1), "=r"(r2), "=r"(r3) : "r"(addr));
}
__device__ __forceinline__ void ldsm4t(uint32_t& r0, uint32_t& r1,
                                       uint32_t& r2, uint32_t& r3, unsigned addr) {
    asm volatile("ldmatrix.sync.aligned.m8n8.x4.trans.shared.b16 {%0,%1,%2,%3}, [%4];\n"
                 : "=r"(r0), "=r"(r1), "=r"(r2), "=r"(r3) : "r"(addr));
}
// fp16 operands, fp32 accumulate (embed)
__device__ __forceinline__ void mma16816h(float* c, const uint32_t* a,
                                          uint32_t b0, uint32_t b1) {
    asm volatile(
        "mma.sync.aligned.m16n8k16.row.col.f32.f16.f16.f32 "
        "{%0,%1,%2,%3}, {%4,%5,%6,%7}, {%8,%9}, {%0,%1,%2,%3};\n"
        : "+f"(c[0]), "+f"(c[1]), "+f"(c[2]), "+f"(c[3])
        : "r"(a[0]), "r"(a[1]), "r"(a[2]), "r"(a[3]), "r"(b0), "r"(b1));
}
// fp16 operands, fp16 accumulate (sim — half the acc registers)
__device__ __forceinline__ void mma16816hh(uint32_t* c, const uint32_t* a,
                                           uint32_t b0, uint32_t b1) {
    asm volatile(
        "mma.sync.aligned.m16n8k16.row.col.f16.f16.f16.f16 "
        "{%0,%1}, {%2,%3,%4,%5}, {%6,%7}, {%0,%1};\n"
        : "+r"(c[0]), "+r"(c[1])
        : "r"(a[0]), "r"(a[1]), "r"(a[2]), "r"(a[3]), "r"(b0), "r"(b1));
}
__device__ __forceinline__ void cp_async16(unsigned saddr, const void* g) {
    asm volatile("cp.async.cg.shared.global [%0], [%1], 16;\n"
                 :: "r"(saddr), "l"(g) : "memory");
}
__device__ __forceinline__ void cp_commit() {
    asm volatile("cp.async.commit_group;\n" ::: "memory");
}
template <int N> __device__ __forceinline__ void cp_wait() {
    asm volatile("cp.async.wait_group %0;\n" :: "n"(N) : "memory");
}
__device__ __forceinline__ uint32_t smem_u32(const void* p) {
    uint32_t a;
    asm("{ .reg .u64 t; cvta.to.shared.u64 t, %1; cvt.u32.u64 %0, t; }"
        : "=r"(a) : "l"(p));
    return a;
}

// ---------------------------------------------------------------------------
// Kernel 1: projection + bias + L2 normalize, SINGLE-PASS fp16 (R16 proven).
// ---------------------------------------------------------------------------
#define AK 72       // A smem k-stride (144B pitch, conflict-free)
#define WP 136      // W smem n-stride (272B pitch, conflict-free)

__global__ __launch_bounds__(256, 3) void embed_kernel(
    const float* __restrict__ qh, const float* __restrict__ dh,
    const float* __restrict__ W, const float* __restrict__ bias)
{
    extern __shared__ char esm[];
    __half* sW = (__half*)esm;                  // 64 x 136
    __half* sA = sW + 64 * WP;                  // 64 x 72
    float* ssp = (float*)(sA + 64 * AK);        // [64][4]

    const int tid  = threadIdx.x;
    const int lane = tid & 31, warp = tid >> 5;
    const int wm = warp >> 2, wn = warp & 3;

    const unsigned uW = smem_u32(sW);
    const unsigned uA = smem_u32(sA);

    unsigned aoff[2];
#pragma unroll
    for (int mt = 0; mt < 2; mt++)
        aoff[mt] = (unsigned)((wm * 32 + mt * 16 + (lane & 15)) * AK
                              + (lane >> 4) * 8) * 2;
    const int bk = (lane & 7) + ((lane >> 3) & 1) * 8;
    const unsigned bnb = (unsigned)(wn * 32 + (lane >> 4) * 8) * 2;
    const int cbase = (lane & 3) * 2;

    const int row0 = blockIdx.x * 64;
    const float* src = (row0 < N_QTOK)
        ? (qh + (size_t)row0 * HID)
        : (dh + (size_t)(row0 - N_QTOK) * HID);

    float acc[2][4][4];
#pragma unroll
    for (int mt = 0; mt < 2; mt++)
#pragma unroll
        for (int nt = 0; nt < 4; nt++)
#pragma unroll
            for (int r = 0; r < 4; r++) acc[mt][nt][r] = 0.f;

    for (int kc = 0; kc < 4; kc++) {
        const int k0 = kc * 64;
        if (kc) __syncthreads();   // prior kc ldsm reads done

#pragma unroll
        for (int j = 0; j < 8; j++) {
            int f = tid + j * 256, r = f >> 5, c4 = f & 31;
            float4 v = *(const float4*)(W + (size_t)(k0 + r) * DIM + c4 * 4);
            __half2 h0 = __float22half2_rn(make_float2(v.x, v.y));
            __half2 h1 = __float22half2_rn(make_float2(v.z, v.w));
            *(__half2*)&sW[r * WP + c4 * 4]     = h0;
            *(__half2*)&sW[r * WP + c4 * 4 + 2] = h1;
        }
#pragma unroll
        for (int j = 0; j < 4; j++) {
            int f = tid + j * 256, r = f >> 4, cv = f & 15;
            float4 v = *(const float4*)(src + (size_t)r * HID + k0 + cv * 4);
            __half2 h0 = __float22half2_rn(make_float2(v.x, v.y));
            __half2 h1 = __float22half2_rn(make_float2(v.z, v.w));
            *(__half2*)&sA[r * AK + cv * 4]     = h0;
            *(__half2*)&sA[r * AK + cv * 4 + 2] = h1;
        }
        __syncthreads();

#pragma unroll
        for (int ks = 0; ks < 4; ks++) {
            uint32_t a0[4], a1[4];
            ldsm4(a0[0], a0[1], a0[2], a0[3], uA + aoff[0] + ks * 32);
            ldsm4(a1[0], a1[1], a1[2], a1[3], uA + aoff[1] + ks * 32);
            const unsigned be = (unsigned)((ks * 16 + bk) * WP) * 2 + bnb;
            uint32_t b0[4], b1[4];
            ldsm4t(b0[0], b0[1], b0[2], b0[3], uW + be);
            ldsm4t(b1[0], b1[1], b1[2], b1[3], uW + be + 32);

            mma16816h(acc[0][0], a0, b0[0], b0[1]);
            mma16816h(acc[0][1], a0, b0[2], b0[3]);
            mma16816h(acc[0][2], a0, b1[0], b1[1]);
            mma16816h(acc[0][3], a0, b1[2], b1[3]);
            mma16816h(acc[1][0], a1, b0[0], b0[1]);
            mma16816h(acc[1][1], a1, b0[2], b0[3]);
            mma16816h(acc[1][2], a1, b1[0], b1[1]);
            mma16816h(acc[1][3], a1, b1[2], b1[3]);
        }
    }

#pragma unroll
    for (int mt = 0; mt < 2; mt++) {
        float s0 = 0.f, s1 = 0.f;
#pragma unroll
        for (int nt = 0; nt < 4; nt++) {
            float2 bv = *(const float2*)(bias + wn * 32 + nt * 8 + cbase);
            acc[mt][nt][0] += bv.x; acc[mt][nt][1] += bv.y;
            acc[mt][nt][2] += bv.x; acc[mt][nt][3] += bv.y;
            s0 += acc[mt][nt][0] * acc[mt][nt][0]
                + acc[mt][nt][1] * acc[mt][nt][1];
            s1 += acc[mt][nt][2] * acc[mt][nt][2]
                + acc[mt][nt][3] * acc[mt][nt][3];
        }
        s0 += __shfl_xor_sync(0xffffffffu, s0, 1);
        s0 += __shfl_xor_sync(0xffffffffu, s0, 2);
        s1 += __shfl_xor_sync(0xffffffffu, s1, 1);
        s1 += __shfl_xor_sync(0xffffffffu, s1, 2);
        if ((lane & 3) == 0) {
            ssp[(wm * 32 + mt * 16 + (lane >> 2)) * 4 + wn] = s0;
            ssp[(wm * 32 + mt * 16 + 8 + (lane >> 2)) * 4 + wn] = s1;
        }
    }
    __syncthreads();
#pragma unroll
    for (int mt = 0; mt < 2; mt++) {
        const int r0 = wm * 32 + mt * 16 + (lane >> 2);
        const int r1 = r0 + 8;
        float ss0 = ssp[r0 * 4] + ssp[r0 * 4 + 1]
                  + ssp[r0 * 4 + 2] + ssp[r0 * 4 + 3];
        float ss1 = ssp[r1 * 4] + ssp[r1 * 4 + 1]
                  + ssp[r1 * 4 + 2] + ssp[r1 * 4 + 3];
        float inv0 = 1.f / fmaxf(sqrtf(ss0), 1e-12f);
        float inv1 = 1.f / fmaxf(sqrtf(ss1), 1e-12f);
#pragma unroll
        for (int nt = 0; nt < 4; nt++) {
            __half2 vA = __float22half2_rn(
                make_float2(acc[mt][nt][0] * inv0, acc[mt][nt][1] * inv0));
            __half2 vB = __float22half2_rn(
                make_float2(acc[mt][nt][2] * inv1, acc[mt][nt][3] * inv1));
            *(__half2*)(g_emb + (size_t)(row0 + r0) * DIM
                        + wn * 32 + nt * 8 + cbase) = vA;
            *(__half2*)(g_emb + (size_t)(row0 + r1) * DIM
                        + wn * 32 + nt * 8 + cbase) = vB;
        }
    }
}

// ---------------------------------------------------------------------------
// Kernel 2: PERSISTENT fused similarity GEMM + max_t + sum_s.
// fp16 ACCUMULATORS: acc = 2 regs/tile (32 total, was 64) — releases the
// 128-reg ceiling; f16-acc HMMA may also be double-rate. Max-reduce with
// __hmax2 on packed pairs; final sum stays fp32.
// ---------------------------------------------------------------------------
#define DSTR 136

__global__ __launch_bounds__(256, 2) void sim_kernel(float* __restrict__ out)
{
    extern __shared__ char smem[];
    __half* sQ = (__half*)smem;                            // 128 x 136
    __half* sD = sQ + 128 * DSTR;                          // 2 x (128 x 136)
    float* red = (float*)(sD + 2 * 128 * DSTR);            // [2][8 warps][32]

    const int tid  = threadIdx.x;
    const int lane = tid & 31, warp = tid >> 5;
    const int wm = warp >> 1, wn = warp & 1;
    const unsigned G = gridDim.x, c = blockIdx.x;
    unsigned s = (4096u * c) / G;
    const unsigned e = (4096u * (c + 1)) / G;

    const unsigned uQ = smem_u32(sQ);
    const unsigned uD = smem_u32(sD);

    unsigned aoff[2];
#pragma unroll
    for (int mt = 0; mt < 2; mt++) {
        int row = wm * 32 + mt * 16 + (lane & 15);
        int col = (lane >> 4) * 8;
        aoff[mt] = uQ + (unsigned)(row * DSTR + col) * 2;
    }
    unsigned boff[4];
#pragma unroll
    for (int g = 0; g < 4; g++) {
        int row = wn * 64 + g * 16 + (lane & 7) + (lane >> 4) * 8;
        int col = ((lane >> 3) & 1) * 8;
        boff[g] = (unsigned)(row * DSTR + col) * 2;
    }

    while (s < e) {
        const unsigned qg = s >> 7;
        const unsigned seg_e = min(e, (qg + 1) << 7);
        const int n = (int)(seg_e - s);
        const unsigned qb0 = qg * 4;
        const unsigned db_base = s & 127;

        {   // load Q tile for this segment
            const __half* qsrc = g_emb + (size_t)qg * 128 * DIM;
#pragma unroll
            for (int j = 0; j < 8; j++) {
                int f = tid + j * 256, r = f >> 4, c8 = f & 15;
                *(uint4*)(sQ + r * DSTR + c8 * 8) =
                    *(const uint4*)(qsrc + (size_t)r * DIM + c8 * 8);
            }
        }
        {   // prefetch first doc tile of segment into buffer 0
            const __half* dsrc =
                g_emb + (size_t)(N_QTOK + db_base * 128) * DIM;
#pragma unroll
            for (int j = 0; j < 8; j++) {
                int f = tid + j * 256, r = f >> 4, c8 = f & 15;
                cp_async16(uD + (unsigned)(r * DSTR + c8 * 8) * 2,
                           dsrc + (size_t)r * DIM + c8 * 8);
            }
            cp_commit();
        }

        for (int j = 0; j < n; j++) {
            if (j + 1 < n) {
                const __half* dsrc =
                    g_emb + (size_t)(N_QTOK + (db_base + j + 1) * 128) * DIM;
                const unsigned dst =
                    uD + (unsigned)((j + 1) & 1) * (128 * DSTR * 2);
#pragma unroll
                for (int t = 0; t < 8; t++) {
                    int f = tid + t * 256, r = f >> 4, c8 = f & 15;
                    cp_async16(dst + (unsigned)(r * DSTR + c8 * 8) * 2,
                               dsrc + (size_t)r * DIM + c8 * 8);
                }
                cp_commit();
                cp_wait<1>();
            } else {
                cp_wait<0>();
            }
            __syncthreads();   // S1: tile j data + Q visible

            if (j >= 1 && tid < 128) {   // finalize unit j-1
                const int qb = tid >> 5, row = tid & 31;
                const float* rb = red + ((j - 1) & 1) * 256;
                float v = fmaxf(rb[(qb * 2) * 32 + row],
                                rb[(qb * 2 + 1) * 32 + row]);
#pragma unroll
                for (int off = 16; off >= 1; off >>= 1)
                    v += __shfl_xor_sync(0xffffffffu, v, off);
                if (lane == 0)
                    out[(size_t)(qb0 + qb) * 128 + (db_base + j - 1)] = v;
            }

            // fp16 accumulators: 2 u32 (4 halves) per mma tile
            uint32_t acc[2][8][2];
#pragma unroll
            for (int mt = 0; mt < 2; mt++)
#pragma unroll
                for (int t = 0; t < 8; t++) {
                    acc[mt][t][0] = 0u; acc[mt][t][1] = 0u;
                }

            const unsigned dbase = uD + (unsigned)(j & 1) * (128 * DSTR * 2);
#pragma unroll
            for (int ks = 0; ks < 8; ks++) {
                uint32_t a[2][4], b[4][4];
                ldsm4(a[0][0], a[0][1], a[0][2], a[0][3], aoff[0] + ks * 32);
                ldsm4(a[1][0], a[1][1], a[1][2], a[1][3], aoff[1] + ks * 32);
#pragma unroll
                for (int g = 0; g < 4; g++)
                    ldsm4(b[g][0], b[g][1], b[g][2], b[g][3],
                          dbase + boff[g] + ks * 32);
#pragma unroll
                for (int mt = 0; mt < 2; mt++)
#pragma unroll
                    for (int t = 0; t < 8; t++)
                        mma16816hh(acc[mt][t], a[mt],
                                   b[t >> 1][(t & 1) * 2],
                                   b[t >> 1][(t & 1) * 2 + 1]);
            }

            // in-warp row-max (packed hmax2) -> red[j&1] (fp32)
            float* rw = red + (j & 1) * 256 + warp * 32;
#pragma unroll
            for (int mt = 0; mt < 2; mt++) {
#pragma unroll
                for (int h = 0; h < 2; h++) {   // h = row half (reg index)
                    __half2 m2 = __floats2half2_rn(-65504.f, -65504.f);
#pragma unroll
                    for (int t = 0; t < 8; t++)
                        m2 = __hmax2(m2, *(__half2*)&acc[mt][t][h]);
                    float m = fmaxf(__low2float(m2), __high2float(m2));
                    m = fmaxf(m, __shfl_xor_sync(0xffffffffu, m, 1));
                    m = fmaxf(m, __shfl_xor_sync(0xffffffffu, m, 2));
                    if ((lane & 3) == 0)
                        rw[mt * 16 + h * 8 + (lane >> 2)] = m;
                }
            }
            __syncthreads();   // S2: red complete; buffers reusable
        }

        // tail: finalize last unit of segment
        if (tid < 128) {
            const int qb = tid >> 5, row = tid & 31;
            const float* rb = red + ((n - 1) & 1) * 256;
            float v = fmaxf(rb[(qb * 2) * 32 + row],
                            rb[(qb * 2 + 1) * 32 + row]);
#pragma unroll
            for (int off = 16; off >= 1; off >>= 1)
                v += __shfl_xor_sync(0xffffffffu, v, off);
            if (lane == 0)
                out[(size_t)(qb0 + qb) * 128 + (db_base + n - 1)] = v;
        }
        __syncthreads();
        s = seg_e;
    }
}

// ---------------------------------------------------------------------------
extern "C" void kernel_launch(void* const* d_in, const int* in_sizes, int n_in,
                              void* d_out, int out_size) {
    const float* qh   = (const float*)d_in[0];
    const float* dh   = (const float*)d_in[1];
    const float* W    = (const float*)d_in[2];
    const float* bias = (const float*)d_in[3];
    float* out = (float*)d_out;

    int sms = 148;
    cudaDeviceGetAttribute(&sms, cudaDevAttrMultiProcessorCount, 0);

    const int ESMEM = 64 * WP * 2 + 64 * AK * 2 + 64 * 4 * 4;   // 27648
    const int SSMEM = 3 * 128 * DSTR * 2 + 2 * 256 * 4;         // 106496
    cudaFuncSetAttribute(embed_kernel,
                         cudaFuncAttributeMaxDynamicSharedMemorySize, ESMEM);
    cudaFuncSetAttribute(sim_kernel,
                         cudaFuncAttributeMaxDynamicSharedMemorySize, SSMEM);

    embed_kernel<<<N_ETILE, 256, ESMEM>>>(qh, dh, W, bias);
    sim_kernel<<<2 * sms, 256, SSMEM>>>(out);
}